// round 16
// baseline (speedup 1.0000x reference)
#include <cuda_runtime.h>
#include <math.h>

// Problem constants (fixed shapes from reference setup_inputs)
#define BN   32
#define NA   24564
#define NCLS 81
#define NO   16
#define TOTROWS (BN * NA)   // 786048

// ---------------- scratch (device globals: no allocation allowed) ----------
// Zero-initialized at module load; k_topk re-zeroes mutable state at the end
// of each run so every graph replay starts clean (no init kernel).
__device__ float              g_negconf[BN * NA];
__device__ float              g_lse[BN * NA];      // log-sum-exp per row
__device__ int2               g_argm[BN * NA];     // per-anchor (biou bits, best obj)
__device__ unsigned long long g_best[BN * NO];
__device__ int                g_npos[BN];
__device__ int                g_npos_total;
__device__ int                g_done;
__device__ double             g_posconf;
__device__ double             g_sl1;
__device__ double             g_hard;

// ---------------- fused match pass A (independent of k_soft) ---------------
#define MA_T   256
#define MA_A   4
#define MA_BLK (MA_T * MA_A)                   // 1024
#define MA_NB  ((NA + MA_BLK - 1) / MA_BLK)    // 24

__global__ void __launch_bounds__(MA_T) k_matchA(const float4* __restrict__ boxes,
                                                 const float4* __restrict__ dboxes)
{
    int b    = blockIdx.y;
    int base = blockIdx.x * MA_BLK;
    int tid  = threadIdx.x;

    __shared__ float4 sbox[NO];
    __shared__ float  sarea[NO];
    __shared__ unsigned long long sb[NO];
    if (tid < NO) {
        float4 bx = boxes[b * NO + tid];
        sbox[tid]  = bx;
        sarea[tid] = (bx.z - bx.x) * (bx.w - bx.y);
        sb[tid]    = 0ull;
    }
    __syncthreads();

    float dx0[MA_A], dy0[MA_A], dx1[MA_A], dy1[MA_A], areaB[MA_A];
#pragma unroll
    for (int i = 0; i < MA_A; i++) {
        int n = base + i * MA_T + tid;
        if (n < NA) {
            float4 d = __ldg(&dboxes[n]);
            dx0[i] = d.x - d.z * 0.5f; dy0[i] = d.y - d.w * 0.5f;
            dx1[i] = d.x + d.z * 0.5f; dy1[i] = d.y + d.w * 0.5f;
            areaB[i] = (dx1[i] - dx0[i]) * (dy1[i] - dy0[i]);
        } else {
            dx0[i] = 3.0f; dy0[i] = 3.0f; dx1[i] = 3.0f; dy1[i] = 3.0f;
            areaB[i] = 0.0f;
        }
    }

    unsigned akey[MA_A] = {0u, 0u, 0u, 0u};       // (bits & ~15) | o
    float    biou[MA_A] = {0.f, 0.f, 0.f, 0.f};   // exact max for threshold

#pragma unroll 4
    for (int o = 0; o < NO; o++) {
        float4 a = sbox[o];
        float  sA = sarea[o];
        unsigned k32 = 0u;                        // (bits & ~3) | i
#pragma unroll
        for (int i = 0; i < MA_A; i++) {
            float ltx = fmaxf(a.x, dx0[i]), lty = fmaxf(a.y, dy0[i]);
            float rbx = fminf(a.z, dx1[i]), rby = fminf(a.w, dy1[i]);
            float w = fmaxf(rbx - ltx, 0.0f), h = fmaxf(rby - lty, 0.0f);
            float inter = w * h;
            float v = __fdividef(inter, sA + areaB[i] - inter);
            unsigned bits = __float_as_uint(v);
            biou[i] = fmaxf(biou[i], v);
            akey[i] = umax(akey[i], (bits & 0xFFFFFFF0u) | (unsigned)o);
            k32     = umax(k32,     (bits & 0xFFFFFFFCu) | (unsigned)i);
        }
        unsigned i  = k32 & 3u;
        unsigned n  = (unsigned)(base + (int)i * MA_T + tid);
        unsigned long long key =
            ((unsigned long long)(k32 & 0xFFFFFFFCu) << 32) |
            (unsigned long long)(0xFFFFFFFFu - n);
        if (key > sb[o]) atomicMax(&sb[o], key);
    }

#pragma unroll
    for (int i = 0; i < MA_A; i++) {
        int n = base + i * MA_T + tid;
        if (n < NA)
            g_argm[b * NA + n] =
                make_int2(__float_as_int(biou[i]), (int)(akey[i] & 15u));
    }

    __syncthreads();
    if (tid < NO) {
        unsigned long long k = sb[tid];
        if (k > g_best[b * NO + tid])
            atomicMax(&g_best[b * NO + tid], k);
    }
}

// ---------------- k_soft: pure log-sum-exp sweep (HBM-bound, no match dep) -
#define B_T  256
#define RPW  4

__global__ void __launch_bounds__(B_T) k_soft(const float* __restrict__ cls)
{
    const unsigned FULL = 0xffffffffu;
    int wg   = (blockIdx.x * B_T + threadIdx.x) >> 5;
    int lane = threadIdx.x & 31;
    int row0 = wg * RPW;

    const float* p = cls + (size_t)row0 * NCLS;
    float v0[RPW], v1[RPW], v2[RPW];
#pragma unroll
    for (int r = 0; r < RPW; r++) {                      // 12 front-batched LDGs
        v0[r] = __ldg(p + r * NCLS + lane);
        v1[r] = __ldg(p + r * NCLS + 32 + lane);
        v2[r] = (lane < 17) ? __ldg(p + r * NCLS + 64 + lane) : 0.0f;
    }
    float s[RPW];
#pragma unroll
    for (int r = 0; r < RPW; r++)
        s[r] = __expf(v0[r]) + __expf(v1[r]) +
               ((lane < 17) ? __expf(v2[r]) : 0.0f);
#pragma unroll
    for (int o = 16; o > 0; o >>= 1) {                   // 4 interleaved chains
#pragma unroll
        for (int r = 0; r < RPW; r++)
            s[r] += __shfl_xor_sync(FULL, s[r], o);
    }
    if (lane == 0)
        ((float4*)g_lse)[wg] = make_float4(__logf(s[0]), __logf(s[1]),
                                           __logf(s[2]), __logf(s[3]));
}

// ---------------- k_rest: matchB + conf + loc loss (light epilogue) --------
__global__ void __launch_bounds__(B_T) k_rest(const float*  __restrict__ cls,
                                              const float*  __restrict__ locs,
                                              const float4* __restrict__ boxes,
                                              const int*    __restrict__ labels,
                                              const float4* __restrict__ dboxes)
{
    const unsigned FULL = 0xffffffffu;
    int wg   = (blockIdx.x * B_T + threadIdx.x) >> 5;
    int lane = threadIdx.x & 31;
    int wip  = threadIdx.x >> 5;
    int row0 = wg * RPW;
    int b    = row0 / NA;          // warp-uniform
    int n0   = row0 - b * NA;

    float4   obox = make_float4(0.f, 0.f, 0.f, 0.f);
    int      olab = 0;
    unsigned osov = 0xFFFFFFFFu;
    if (lane < NO) {
        obox = __ldg(&boxes[b * NO + lane]);
        olab = __ldg(&labels[b * NO + lane]);
        unsigned long long be = g_best[b * NO + lane];
        osov = 0xFFFFFFFFu - (unsigned)(be & 0xFFFFFFFFull);
    }
    int2 am = make_int2(0, 0);
    if (lane < RPW) am = g_argm[row0 + lane];
    float4 L = __ldg((const float4*)&g_lse[row0]);       // broadcast load
    float lse[RPW] = {L.x, L.y, L.z, L.w};

    // -------- match-B: labels in-register --------
    int lbl[RPW];
    int bo_[RPW];
#pragma unroll
    for (int r = 0; r < RPW; r++) {
        int n_r = n0 + r;
        int ax  = __shfl_sync(FULL, am.x, r);
        int ay  = __shfl_sync(FULL, am.y, r);
        unsigned bal = __ballot_sync(FULL, lane < NO && osov == (unsigned)n_r);
        int   bo;  float biou;
        if (bal) { bo = 31 - __clz(bal); biou = 1.0f; }  // highest o = last write
        else     { bo = ay; biou = __int_as_float(ax); }
        int l = (biou < 0.5f) ? 0 : __shfl_sync(FULL, olab, bo);
        lbl[r] = l; bo_[r] = bo;
    }

    // -------- fetch the selected logit (one 4B gather per row) --------
    float myLogit = 0.0f;
#pragma unroll
    for (int r = 0; r < RPW; r++)
        if (lane == r)
            myLogit = __ldg(&cls[(size_t)(row0 + r) * NCLS + lbl[r]]);

    float nc[RPW];
#pragma unroll
    for (int r = 0; r < RPW; r++) {
        float logit = __shfl_sync(FULL, myLogit, r);
        float conf  = lse[r] - logit;
        nc[r] = (lbl[r] != 0) ? -conf : conf;            // positives stash -conf
    }

    // -------- positives: loc loss + pos_conf (rare path, warp-uniform) -----
    __shared__ float sp[B_T / 32], ss[B_T / 32];
    float myp = 0.0f, mys = 0.0f;
    int cnt = 0;
#pragma unroll
    for (int r = 0; r < RPW; r++) {
        if (lbl[r] != 0) {                               // warp-uniform condition
            cnt++;
            float ax0 = __shfl_sync(FULL, obox.x, bo_[r]);
            float ay0 = __shfl_sync(FULL, obox.y, bo_[r]);
            float ax1 = __shfl_sync(FULL, obox.z, bo_[r]);
            float ay1 = __shfl_sync(FULL, obox.w, bo_[r]);
            float4 d  = __ldg(&dboxes[n0 + r]);
            float bcx = (ax1 + ax0) / 2.0f, bcy = (ay1 + ay0) / 2.0f;
            float bw  = ax1 - ax0,          bh  = ay1 - ay0;
            float tx = (bcx - d.x) / (d.z / 10.0f + 1e-6f);
            float ty = (bcy - d.y) / (d.w / 10.0f + 1e-6f);
            float tz = logf(bw / d.z + 1e-6f) * 5.0f;
            float tw = logf(bh / d.w + 1e-6f) * 5.0f;
            if (lane == 0) {
                myp += -nc[r];                           // recover conf
                float4 lp = __ldg((const float4*)(locs + (size_t)(row0 + r) * 4));
                float acc = 0.0f, dd;
                dd = fabsf(lp.x - tx); acc += (dd < 1.0f) ? 0.5f * dd * dd : dd - 0.5f;
                dd = fabsf(lp.y - ty); acc += (dd < 1.0f) ? 0.5f * dd * dd : dd - 0.5f;
                dd = fabsf(lp.z - tz); acc += (dd < 1.0f) ? 0.5f * dd * dd : dd - 0.5f;
                dd = fabsf(lp.w - tw); acc += (dd < 1.0f) ? 0.5f * dd * dd : dd - 0.5f;
                mys += acc;
            }
            nc[r] = 0.0f;                                // negconf = 0 for positives
        }
    }
    if (lane == 0) {
        ((float4*)g_negconf)[wg] = make_float4(nc[0], nc[1], nc[2], nc[3]);
        sp[wip] = myp; ss[wip] = mys;
        if (cnt) {
            atomicAdd(&g_npos[b], cnt);
            atomicAdd(&g_npos_total, cnt);
        }
    }
    __syncthreads();
    if (threadIdx.x == 0) {
        float tp = 0.0f, ts = 0.0f;
#pragma unroll
        for (int i = 0; i < B_T / 32; i++) { tp += sp[i]; ts += ss[i]; }
        if (tp != 0.0f) atomicAdd(&g_posconf, (double)tp);
        if (ts != 0.0f) atomicAdd(&g_sl1, (double)ts);
    }
}

// ---------------- top-k: register-cached exact 4-pass radix select ---------
// Also RESETS all global state at the end (next graph replay starts clean).
#define C_T   1024
#define NA4   (NA / 4)     // 6141 exactly
#define VPT   6            // float4 per thread (6*1024 = 6144 >= 6141)

__device__ __forceinline__ int block_suffix_after(int val, int tid, int* tmp32)
{
    const unsigned FULL = 0xffffffffu;
    int lane = tid & 31, w = tid >> 5;
    __syncthreads();                       // protect tmp32 reuse
    int s = val;                           // inclusive suffix within warp
#pragma unroll
    for (int o = 1; o < 32; o <<= 1) {
        int v = __shfl_down_sync(FULL, s, o);
        if (lane + o < 32) s += v;
    }
    if (lane == 0) tmp32[w] = s;           // warp totals
    __syncthreads();
    if (tid < 32) {
        int wv = tmp32[tid];
        int t2 = wv;
#pragma unroll
        for (int o = 1; o < 32; o <<= 1) {
            int v = __shfl_down_sync(FULL, t2, o);
            if (lane + o < 32) t2 += v;
        }
        tmp32[tid] = t2 - wv;              // suffix strictly after warp tid
    }
    __syncthreads();
    return tmp32[w] + (s - val);           // later warps + higher lanes in warp
}

__global__ void __launch_bounds__(C_T) k_topk(float* __restrict__ out)
{
    int b = blockIdx.x;
    int tid = threadIdx.x;
    int wid = tid >> 5;

    __shared__ unsigned whist[32][256];    // per-warp private histograms (32KB)
    __shared__ unsigned hist[256];
    __shared__ int      tmp32[32];
    __shared__ int      s_digit, s_rem, s_last;
    __shared__ double   sdbl[32];
    __shared__ int      sint[32];

    int k = 3 * g_npos[b];
    if (k > NA) k = NA;

    // reset per-batch state for the NEXT graph replay
    if (tid < NO) g_best[b * NO + tid] = 0ull;
    if (tid == 0) g_npos[b] = 0;

    if (k > 0) {
        const float4* v4 = (const float4*)&g_negconf[b * NA];
        float  vals[VPT * 4];
        bool   vok[VPT];
#pragma unroll
        for (int i = 0; i < VPT; i++) {
            int j = tid + i * C_T;
            vok[i] = (j < NA4);
            float4 x = vok[i] ? __ldg(&v4[j]) : make_float4(0.f, 0.f, 0.f, 0.f);
            vals[i * 4 + 0] = x.x; vals[i * 4 + 1] = x.y;
            vals[i * 4 + 2] = x.z; vals[i * 4 + 3] = x.w;
        }

        unsigned prefix = 0, pmask = 0;
        int rem = k;
#pragma unroll
        for (int p = 3; p >= 0; --p) {
            int sh = p * 8;
            unsigned* hrow = &whist[0][0];
#pragma unroll
            for (int i = 0; i < 8; i++) hrow[tid + i * C_T] = 0u;
            __syncthreads();
            unsigned* myh = whist[wid];
#pragma unroll
            for (int i = 0; i < VPT; i++) {
#pragma unroll
                for (int c = 0; c < 4; c++) {
                    unsigned bits = __float_as_uint(vals[i * 4 + c]);
                    if (vok[i] && (bits & pmask) == prefix)
                        atomicAdd(&myh[(bits >> sh) & 255u], 1u);
                }
            }
            __syncthreads();
            int myc = 0;
            if (tid < 256) {
                unsigned c = 0;
#pragma unroll
                for (int w = 0; w < 32; w++) c += whist[w][tid];
                hist[tid] = c;
                myc = (int)c;
            }
            int sufA = block_suffix_after(myc, tid, tmp32);
            if (tid < 256 && sufA < rem && sufA + myc >= rem) {  // unique thread
                s_digit = tid; s_rem = rem - sufA;
            }
            __syncthreads();
            prefix |= ((unsigned)s_digit) << sh;
            pmask  |= 0xFFu << sh;
            rem = s_rem;
            __syncthreads();
        }

        double sg = 0.0; int cg = 0;
#pragma unroll
        for (int i = 0; i < VPT; i++) {
#pragma unroll
            for (int c = 0; c < 4; c++) {
                unsigned bits = __float_as_uint(vals[i * 4 + c]);
                if (vok[i] && bits > prefix) { sg += (double)vals[i * 4 + c]; cg++; }
            }
        }
#pragma unroll
        for (int o = 16; o > 0; o >>= 1) {
            sg += __shfl_xor_sync(0xffffffffu, sg, o);
            cg += __shfl_xor_sync(0xffffffffu, cg, o);
        }
        if ((tid & 31) == 0) { sdbl[wid] = sg; sint[wid] = cg; }
        __syncthreads();
        if (tid == 0) {
            double s2 = 0.0; int c2 = 0;
#pragma unroll
            for (int i = 0; i < 32; i++) { s2 += sdbl[i]; c2 += sint[i]; }
            double t = (double)__uint_as_float(prefix);
            atomicAdd(&g_hard, s2 + (double)(k - c2) * t);   // exact ties
        }
    }

    // completion ticket: last block finalizes the scalar loss + resets scalars
    __threadfence();
    if (tid == 0) {
        int t = atomicAdd(&g_done, 1);
        s_last = (t == BN - 1);
    }
    __syncthreads();
    if (tid == 0 && s_last) {
        double npt  = (double)(*(volatile int*)&g_npos_total);
        double sl1  = *(volatile double*)&g_sl1;
        double pc   = *(volatile double*)&g_posconf;
        double hd   = *(volatile double*)&g_hard;
        double loc  = sl1 / (npt * 4.0);
        double conf = (hd + pc) / npt;
        out[0] = (float)(0.5 * loc + conf);
        g_posconf = 0.0; g_sl1 = 0.0; g_hard = 0.0;
        g_npos_total = 0; g_done = 0;
    }
}

// ---------------- launcher: fork matchA alongside the softmax sweep --------
extern "C" void kernel_launch(void* const* d_in, const int* in_sizes, int n_in,
                              void* d_out, int out_size)
{
    (void)in_sizes; (void)n_in; (void)out_size;
    const float*  locs   = (const float*)d_in[0];
    const float*  cls    = (const float*)d_in[1];
    const float4* boxes  = (const float4*)d_in[2];
    const int*    labels = (const int*)d_in[3];
    const float4* dboxes = (const float4*)d_in[4];

    int blocksB = TOTROWS / (RPW * (B_T / 32));   // 24564, exact

    cudaStream_t s2;
    cudaEvent_t  e1, e2;
    cudaStreamCreateWithFlags(&s2, cudaStreamNonBlocking);
    cudaEventCreateWithFlags(&e1, cudaEventDisableTiming);
    cudaEventCreateWithFlags(&e2, cudaEventDisableTiming);

    // fork: matchA on s2, concurrent with k_soft on the main stream
    cudaEventRecord(e1, 0);
    cudaStreamWaitEvent(s2, e1, 0);
    dim3 gm(MA_NB, BN);
    k_matchA<<<gm, MA_T, 0, s2>>>(boxes, dboxes);
    cudaEventRecord(e2, s2);

    k_soft<<<blocksB, B_T>>>(cls);                // HBM sweep hides matchA

    // join: epilogue needs both
    cudaStreamWaitEvent(0, e2, 0);
    k_rest<<<blocksB, B_T>>>(cls, locs, boxes, labels, dboxes);
    k_topk<<<BN, C_T>>>((float*)d_out);

    cudaEventDestroy(e1);
    cudaEventDestroy(e2);
    cudaStreamDestroy(s2);
}

// round 17
// speedup vs baseline: 1.8445x; 1.8445x over previous
#include <cuda_runtime.h>
#include <math.h>

// Problem constants (fixed shapes from reference setup_inputs)
#define BN   32
#define NA   24564
#define NCLS 81
#define NO   16
#define TOTROWS (BN * NA)   // 786048

// ---------------- scratch (device globals: no allocation allowed) ----------
// Zero-initialized at module load; k_topk re-zeroes mutable state at the end
// of each run so every graph replay starts clean (no init kernel).
__device__ float              g_negconf[BN * NA];
__device__ int2               g_argm[BN * NA];     // per-anchor (biou bits, best obj)
__device__ unsigned long long g_best[BN * NO];
__device__ int                g_npos[BN];
__device__ int                g_npos_total;
__device__ int                g_done;
__device__ double             g_posconf;
__device__ double             g_sl1;
__device__ double             g_hard;

// ---------------- fused match pass A ---------------------------------------
// Objects OUTER, 4 anchors INNER (anchor geometry in registers; sbox LDS
// amortized over 4 anchors). Argmax via integer keys: IoU >= 0 so float
// order == uint order; low mantissa bits carry the index.
#define MA_T   256
#define MA_A   4
#define MA_BLK (MA_T * MA_A)                   // 1024
#define MA_NB  ((NA + MA_BLK - 1) / MA_BLK)    // 24

__global__ void __launch_bounds__(MA_T) k_matchA(const float4* __restrict__ boxes,
                                                 const float4* __restrict__ dboxes)
{
    int b    = blockIdx.y;
    int base = blockIdx.x * MA_BLK;
    int tid  = threadIdx.x;

    __shared__ float4 sbox[NO];
    __shared__ float  sarea[NO];
    __shared__ unsigned long long sb[NO];
    if (tid < NO) {
        float4 bx = boxes[b * NO + tid];
        sbox[tid]  = bx;
        sarea[tid] = (bx.z - bx.x) * (bx.w - bx.y);
        sb[tid]    = 0ull;
    }
    __syncthreads();

    float dx0[MA_A], dy0[MA_A], dx1[MA_A], dy1[MA_A], areaB[MA_A];
#pragma unroll
    for (int i = 0; i < MA_A; i++) {
        int n = base + i * MA_T + tid;
        if (n < NA) {
            float4 d = __ldg(&dboxes[n]);
            dx0[i] = d.x - d.z * 0.5f; dy0[i] = d.y - d.w * 0.5f;
            dx1[i] = d.x + d.z * 0.5f; dy1[i] = d.y + d.w * 0.5f;
            areaB[i] = (dx1[i] - dx0[i]) * (dy1[i] - dy0[i]);
        } else {
            dx0[i] = 3.0f; dy0[i] = 3.0f; dx1[i] = 3.0f; dy1[i] = 3.0f;
            areaB[i] = 0.0f;
        }
    }

    unsigned akey[MA_A] = {0u, 0u, 0u, 0u};       // (bits & ~15) | o
    float    biou[MA_A] = {0.f, 0.f, 0.f, 0.f};   // exact max for threshold

#pragma unroll 4
    for (int o = 0; o < NO; o++) {
        float4 a = sbox[o];
        float  sA = sarea[o];
        unsigned k32 = 0u;                        // (bits & ~3) | i
#pragma unroll
        for (int i = 0; i < MA_A; i++) {
            float ltx = fmaxf(a.x, dx0[i]), lty = fmaxf(a.y, dy0[i]);
            float rbx = fminf(a.z, dx1[i]), rby = fminf(a.w, dy1[i]);
            float w = fmaxf(rbx - ltx, 0.0f), h = fmaxf(rby - lty, 0.0f);
            float inter = w * h;
            float v = __fdividef(inter, sA + areaB[i] - inter);
            unsigned bits = __float_as_uint(v);
            biou[i] = fmaxf(biou[i], v);
            akey[i] = umax(akey[i], (bits & 0xFFFFFFF0u) | (unsigned)o);
            k32     = umax(k32,     (bits & 0xFFFFFFFCu) | (unsigned)i);
        }
        unsigned i  = k32 & 3u;
        unsigned n  = (unsigned)(base + (int)i * MA_T + tid);
        unsigned long long key =
            ((unsigned long long)(k32 & 0xFFFFFFFCu) << 32) |
            (unsigned long long)(0xFFFFFFFFu - n);
        if (key > sb[o]) atomicMax(&sb[o], key);
    }

#pragma unroll
    for (int i = 0; i < MA_A; i++) {
        int n = base + i * MA_T + tid;
        if (n < NA)
            g_argm[b * NA + n] =
                make_int2(__float_as_int(biou[i]), (int)(akey[i] & 15u));
    }

    __syncthreads();
    if (tid < NO) {
        unsigned long long k = sb[tid];
        if (k > g_best[b * NO + tid])
            atomicMax(&g_best[b * NO + tid], k);
    }
}

// ------- fused: match-B (override/label/encode) + softmax conf + loc loss --
// ILP=4 (proven sweet spot). Positive accumulations go straight to global
// double atomics per warp (rare + well-spread): no block barrier/reduction.
#define B_T  256
#define RPW  4

__global__ void __launch_bounds__(B_T) k_conf(const float*  __restrict__ cls,
                                              const float*  __restrict__ locs,
                                              const float4* __restrict__ boxes,
                                              const int*    __restrict__ labels,
                                              const float4* __restrict__ dboxes)
{
    const unsigned FULL = 0xffffffffu;
    int wg   = (blockIdx.x * B_T + threadIdx.x) >> 5;   // global warp id
    int lane = threadIdx.x & 31;
    int row0 = wg * RPW;
    int b    = row0 / NA;          // warp-uniform
    int n0   = row0 - b * NA;

    float4   obox = make_float4(0.f, 0.f, 0.f, 0.f);
    int      olab = 0;
    unsigned osov = 0xFFFFFFFFu;
    if (lane < NO) {
        obox = __ldg(&boxes[b * NO + lane]);
        olab = __ldg(&labels[b * NO + lane]);
        unsigned long long be = g_best[b * NO + lane];
        osov = 0xFFFFFFFFu - (unsigned)(be & 0xFFFFFFFFull);
    }
    int2 am = make_int2(0, 0);
    if (lane < RPW) am = g_argm[row0 + lane];

    // -------- softmax logits (the HBM-dominant part) --------
    const float* p = cls + (size_t)row0 * NCLS;
    float v0[RPW], v1[RPW], v2[RPW];
#pragma unroll
    for (int r = 0; r < RPW; r++) {                      // 12 front-batched LDGs
        v0[r] = __ldg(p + r * NCLS + lane);
        v1[r] = __ldg(p + r * NCLS + 32 + lane);
        v2[r] = (lane < 17) ? __ldg(p + r * NCLS + 64 + lane) : 0.0f;
    }
    float s[RPW];
#pragma unroll
    for (int r = 0; r < RPW; r++)
        s[r] = __expf(v0[r]) + __expf(v1[r]) +
               ((lane < 17) ? __expf(v2[r]) : 0.0f);
#pragma unroll
    for (int o = 16; o > 0; o >>= 1) {                   // 4 interleaved chains
#pragma unroll
        for (int r = 0; r < RPW; r++)
            s[r] += __shfl_xor_sync(FULL, s[r], o);
    }

    // -------- match-B: labels in-register --------
    int   lbl[RPW];
    int   bo_[RPW];
    float nc[RPW];
#pragma unroll
    for (int r = 0; r < RPW; r++) {
        int n_r = n0 + r;
        int ax  = __shfl_sync(FULL, am.x, r);
        int ay  = __shfl_sync(FULL, am.y, r);
        unsigned bal = __ballot_sync(FULL, lane < NO && osov == (unsigned)n_r);
        int   bo;  float biou;
        if (bal) { bo = 31 - __clz(bal); biou = 1.0f; }  // highest o = last write
        else     { bo = ay; biou = __int_as_float(ax); }
        int l = (biou < 0.5f) ? 0 : __shfl_sync(FULL, olab, bo);
        lbl[r] = l; bo_[r] = bo;
    }

#pragma unroll
    for (int r = 0; r < RPW; r++) {
        float sel = (lbl[r] < 32) ? v0[r] : ((lbl[r] < 64) ? v1[r] : v2[r]);
        float logit = __shfl_sync(FULL, sel, lbl[r] & 31);
        float conf  = __logf(s[r]) - logit;
        nc[r] = (lbl[r] != 0) ? -conf : conf;            // positives stash -conf
    }

    // -------- positives: loc loss + pos_conf (rare path, warp-uniform) -----
    float myp = 0.0f, mys = 0.0f;
    int cnt = 0;
#pragma unroll
    for (int r = 0; r < RPW; r++) {
        if (lbl[r] != 0) {                               // warp-uniform condition
            cnt++;
            float ax0 = __shfl_sync(FULL, obox.x, bo_[r]);
            float ay0 = __shfl_sync(FULL, obox.y, bo_[r]);
            float ax1 = __shfl_sync(FULL, obox.z, bo_[r]);
            float ay1 = __shfl_sync(FULL, obox.w, bo_[r]);
            float4 d  = __ldg(&dboxes[n0 + r]);
            float bcx = (ax1 + ax0) / 2.0f, bcy = (ay1 + ay0) / 2.0f;
            float bw  = ax1 - ax0,          bh  = ay1 - ay0;
            float tx = (bcx - d.x) / (d.z / 10.0f + 1e-6f);
            float ty = (bcy - d.y) / (d.w / 10.0f + 1e-6f);
            float tz = logf(bw / d.z + 1e-6f) * 5.0f;
            float tw = logf(bh / d.w + 1e-6f) * 5.0f;
            if (lane == 0) {
                myp += -nc[r];                           // recover conf
                float4 lp = __ldg((const float4*)(locs + (size_t)(row0 + r) * 4));
                float acc = 0.0f, dd;
                dd = fabsf(lp.x - tx); acc += (dd < 1.0f) ? 0.5f * dd * dd : dd - 0.5f;
                dd = fabsf(lp.y - ty); acc += (dd < 1.0f) ? 0.5f * dd * dd : dd - 0.5f;
                dd = fabsf(lp.z - tz); acc += (dd < 1.0f) ? 0.5f * dd * dd : dd - 0.5f;
                dd = fabsf(lp.w - tw); acc += (dd < 1.0f) ? 0.5f * dd * dd : dd - 0.5f;
                mys += acc;
            }
            nc[r] = 0.0f;                                // negconf = 0 for positives
        }
    }
    if (lane == 0) {
        ((float4*)g_negconf)[wg] = make_float4(nc[0], nc[1], nc[2], nc[3]);
        if (cnt) {                                       // rare, well-spread
            atomicAdd(&g_npos[b], cnt);
            atomicAdd(&g_npos_total, cnt);
            atomicAdd(&g_posconf, (double)myp);
            atomicAdd(&g_sl1, (double)mys);
        }
    }
}

// ---------------- top-k: register-cached exact 4-pass radix select ---------
// Also RESETS all global state at the end (next graph replay starts clean).
#define C_T   1024
#define NA4   (NA / 4)     // 6141 exactly
#define VPT   6            // float4 per thread (6*1024 = 6144 >= 6141)

__device__ __forceinline__ int block_suffix_after(int val, int tid, int* tmp32)
{
    const unsigned FULL = 0xffffffffu;
    int lane = tid & 31, w = tid >> 5;
    __syncthreads();                       // protect tmp32 reuse
    int s = val;                           // inclusive suffix within warp
#pragma unroll
    for (int o = 1; o < 32; o <<= 1) {
        int v = __shfl_down_sync(FULL, s, o);
        if (lane + o < 32) s += v;
    }
    if (lane == 0) tmp32[w] = s;           // warp totals
    __syncthreads();
    if (tid < 32) {
        int wv = tmp32[tid];
        int t2 = wv;
#pragma unroll
        for (int o = 1; o < 32; o <<= 1) {
            int v = __shfl_down_sync(FULL, t2, o);
            if (lane + o < 32) t2 += v;
        }
        tmp32[tid] = t2 - wv;              // suffix strictly after warp tid
    }
    __syncthreads();
    return tmp32[w] + (s - val);           // later warps + higher lanes in warp
}

__global__ void __launch_bounds__(C_T) k_topk(float* __restrict__ out)
{
    int b = blockIdx.x;
    int tid = threadIdx.x;
    int wid = tid >> 5;

    __shared__ unsigned whist[32][256];    // per-warp private histograms (32KB)
    __shared__ unsigned hist[256];
    __shared__ int      tmp32[32];
    __shared__ int      s_digit, s_rem, s_last;
    __shared__ double   sdbl[32];
    __shared__ int      sint[32];

    int k = 3 * g_npos[b];
    if (k > NA) k = NA;

    // reset per-batch state for the NEXT graph replay
    if (tid < NO) g_best[b * NO + tid] = 0ull;
    if (tid == 0) g_npos[b] = 0;

    if (k > 0) {
        const float4* v4 = (const float4*)&g_negconf[b * NA];
        float  vals[VPT * 4];
        bool   vok[VPT];
#pragma unroll
        for (int i = 0; i < VPT; i++) {
            int j = tid + i * C_T;
            vok[i] = (j < NA4);
            float4 x = vok[i] ? __ldg(&v4[j]) : make_float4(0.f, 0.f, 0.f, 0.f);
            vals[i * 4 + 0] = x.x; vals[i * 4 + 1] = x.y;
            vals[i * 4 + 2] = x.z; vals[i * 4 + 3] = x.w;
        }

        unsigned prefix = 0, pmask = 0;
        int rem = k;
#pragma unroll
        for (int p = 3; p >= 0; --p) {
            int sh = p * 8;
            unsigned* hrow = &whist[0][0];
#pragma unroll
            for (int i = 0; i < 8; i++) hrow[tid + i * C_T] = 0u;
            __syncthreads();
            unsigned* myh = whist[wid];
#pragma unroll
            for (int i = 0; i < VPT; i++) {
#pragma unroll
                for (int c = 0; c < 4; c++) {
                    unsigned bits = __float_as_uint(vals[i * 4 + c]);
                    if (vok[i] && (bits & pmask) == prefix)
                        atomicAdd(&myh[(bits >> sh) & 255u], 1u);
                }
            }
            __syncthreads();
            int myc = 0;
            if (tid < 256) {
                unsigned c = 0;
#pragma unroll
                for (int w = 0; w < 32; w++) c += whist[w][tid];
                hist[tid] = c;
                myc = (int)c;
            }
            int sufA = block_suffix_after(myc, tid, tmp32);
            if (tid < 256 && sufA < rem && sufA + myc >= rem) {  // unique thread
                s_digit = tid; s_rem = rem - sufA;
            }
            __syncthreads();
            prefix |= ((unsigned)s_digit) << sh;
            pmask  |= 0xFFu << sh;
            rem = s_rem;
            __syncthreads();
        }

        double sg = 0.0; int cg = 0;
#pragma unroll
        for (int i = 0; i < VPT; i++) {
#pragma unroll
            for (int c = 0; c < 4; c++) {
                unsigned bits = __float_as_uint(vals[i * 4 + c]);
                if (vok[i] && bits > prefix) { sg += (double)vals[i * 4 + c]; cg++; }
            }
        }
#pragma unroll
        for (int o = 16; o > 0; o >>= 1) {
            sg += __shfl_xor_sync(0xffffffffu, sg, o);
            cg += __shfl_xor_sync(0xffffffffu, cg, o);
        }
        if ((tid & 31) == 0) { sdbl[wid] = sg; sint[wid] = cg; }
        __syncthreads();
        if (tid == 0) {
            double s2 = 0.0; int c2 = 0;
#pragma unroll
            for (int i = 0; i < 32; i++) { s2 += sdbl[i]; c2 += sint[i]; }
            double t = (double)__uint_as_float(prefix);
            atomicAdd(&g_hard, s2 + (double)(k - c2) * t);   // exact ties
        }
    }

    // completion ticket: last block finalizes the scalar loss + resets scalars
    __threadfence();
    if (tid == 0) {
        int t = atomicAdd(&g_done, 1);
        s_last = (t == BN - 1);
    }
    __syncthreads();
    if (tid == 0 && s_last) {
        double npt  = (double)(*(volatile int*)&g_npos_total);
        double sl1  = *(volatile double*)&g_sl1;
        double pc   = *(volatile double*)&g_posconf;
        double hd   = *(volatile double*)&g_hard;
        double loc  = sl1 / (npt * 4.0);
        double conf = (hd + pc) / npt;
        out[0] = (float)(0.5 * loc + conf);
        g_posconf = 0.0; g_sl1 = 0.0; g_hard = 0.0;
        g_npos_total = 0; g_done = 0;
    }
}

// ---------------- launcher --------------------------------------------------
extern "C" void kernel_launch(void* const* d_in, const int* in_sizes, int n_in,
                              void* d_out, int out_size)
{
    (void)in_sizes; (void)n_in; (void)out_size;
    const float*  locs   = (const float*)d_in[0];
    const float*  cls    = (const float*)d_in[1];
    const float4* boxes  = (const float4*)d_in[2];
    const int*    labels = (const int*)d_in[3];
    const float4* dboxes = (const float4*)d_in[4];

    dim3 gm(MA_NB, BN);
    k_matchA<<<gm, MA_T>>>(boxes, dboxes);
    int blocksB = TOTROWS / (RPW * (B_T / 32));   // 24564, exact
    k_conf<<<blocksB, B_T>>>(cls, locs, boxes, labels, dboxes);
    k_topk<<<BN, C_T>>>((float*)d_out);
}